// round 8
// baseline (speedup 1.0000x reference)
#include <cuda_runtime.h>
#include <cstdint>

#define NB 512
#define NR 196
#define DV 1024
#define DH 512
#define DA 256
#define KC 32
#define TPB 512                 // one CTA = 2 batches (two 256-thread halves)
#define AP 36                   // A smem pitch (floats) -> conflict-free frag loads
#define MT 64                   // M tile rows per chunk
#define A_STAGE (MT * AP)       // 2304 floats (per batch)
#define B_STAGE (KC * DA)       // 8192 floats (fragment-major, shared by both halves)
#define STG (2 * A_STAGE + B_STAGE)   // 12800 floats per stage
#define NST 3                   // pipeline stages (single sync per chunk)
#define NCH 128                 // 4 M-chunks x 32 K-chunks
#define SMEM_FLOATS (NST * STG + 2 * DA + DA + 2 * DA + 2 * 64 + 16)
#define SMEM_BYTES (SMEM_FLOATS * 4)

__device__ float g_Wv[DV * DA];     // tf32-rounded Wv, fragment-major [kc][ks][wn][m][lane][4]
__device__ float g_hproj[NB * DA];

// ---------------- helpers ----------------
static __device__ __forceinline__ uint32_t smem_u32(const void* p) {
    uint32_t a;
    asm("{ .reg .u64 t; cvta.to.shared.u64 t, %1; cvt.u32.u64 %0, t; }" : "=r"(a) : "l"(p));
    return a;
}
static __device__ __forceinline__ void cpa16(uint32_t dst, const void* src) {
    asm volatile("cp.async.cg.shared.global [%0], [%1], 16;" :: "r"(dst), "l"(src));
}
static __device__ __forceinline__ void cpa_commit() {
    asm volatile("cp.async.commit_group;" ::: "memory");
}
template <int N> static __device__ __forceinline__ void cpa_wait() {
    asm volatile("cp.async.wait_group %0;" :: "n"(N) : "memory");
}
static __device__ __forceinline__ void sts_zero16(uint32_t dst) {
    asm volatile("st.shared.v4.b32 [%0], {%1,%1,%1,%1};" :: "r"(dst), "r"(0) : "memory");
}
static __device__ __forceinline__ uint32_t to_tf32(float x) {
    uint32_t r;
    asm("cvt.rna.tf32.f32 %0, %1;" : "=r"(r) : "f"(x));
    return r;
}
static __device__ __forceinline__ void mma8(float* c, const uint32_t* a, uint32_t b0, uint32_t b1) {
    asm volatile(
        "mma.sync.aligned.m16n8k8.row.col.f32.tf32.tf32.f32 "
        "{%0,%1,%2,%3}, {%4,%5,%6,%7}, {%8,%9}, {%0,%1,%2,%3};"
        : "+f"(c[0]), "+f"(c[1]), "+f"(c[2]), "+f"(c[3])
        : "r"(a[0]), "r"(a[1]), "r"(a[2]), "r"(a[3]), "r"(b0), "r"(b1));
}

// ---------------- setup: Wv permute (blocks 0..1023) + hproj (blocks 1024..1535) ----------------
__global__ __launch_bounds__(DA) void setup_kernel(
    const float* __restrict__ Wv,
    const float* __restrict__ hidden, const float* __restrict__ Wh,
    const float* __restrict__ bh)
{
    if (blockIdx.x < 1024) {
        const int idx = blockIdx.x * DA + threadIdx.x;
        const int j    = idx & 3;
        const int lane = (idx >> 2) & 31;
        const int m    = (idx >> 7) & 3;
        const int wn   = (idx >> 9) & 3;
        const int ks   = (idx >> 11) & 3;
        const int kc   = idx >> 13;
        const int col = wn * 64 + 16 * m + 8 * (j >> 1) + (lane >> 2);
        const int k   = kc * 32 + ks * 8 + (lane & 3) + 4 * (j & 1);
        g_Wv[idx] = __uint_as_float(to_tf32(Wv[k * DA + col]));
    } else {
        const int b = blockIdx.x - 1024, a = threadIdx.x;
        const float* h = hidden + b * DH;
        const float* w = Wh + a;
        float acc = bh[a];
#pragma unroll 8
        for (int k = 0; k < DH; k++) acc = fmaf(h[k], w[k * DA], acc);
        g_hproj[b * DA + a] = acc;
    }
}

// ---------------- staging: A for both batches + one shared B ----------------
static __device__ __forceinline__ void stage_chunk(int idx, int sbuf, uint32_t sS,
                                                   const float* __restrict__ vb0,
                                                   const float* __restrict__ vb1, int th) {
    const int mc = idx >> 5, kc = idx & 31;
    const int k0 = kc * KC;
    const uint32_t base = sS + (uint32_t)sbuf * (STG * 4);
#pragma unroll
    for (int i = 0; i < 2; i++) {                 // A both batches: 2 x 64 rows x 8 segs
        int s = th + i * TPB;
        int bt = s >> 9, rem = s & 511;
        int row = rem >> 3, seg = rem & 7;
        int gr = mc * MT + row;
        uint32_t dst = base + (uint32_t)bt * (A_STAGE * 4) + row * (AP * 4) + seg * 16;
        const float* vb = bt ? vb1 : vb0;
        if (gr < NR) cpa16(dst, vb + (size_t)gr * DV + k0 + seg * 4);
        else         sts_zero16(dst);
    }
    const float* bsrc = g_Wv + (size_t)kc * B_STAGE;
    const uint32_t bB = base + 2u * (A_STAGE * 4);
#pragma unroll
    for (int i = 0; i < 4; i++) {                 // B: flat 32KB, staged ONCE for both halves
        int s = th + i * TPB;
        cpa16(bB + s * 16, bsrc + s * 4);
    }
}

// ---------------- fused: one CTA = 2 batches, 3-stage single-sync, online softmax ----------------
__global__ __launch_bounds__(TPB, 1) void fused_kernel(
    const float* __restrict__ visual,
    const float* __restrict__ bv,
    const float* __restrict__ Wa,
    float* __restrict__ out)
{
    extern __shared__ float smem[];
    float* stg  = smem;                          // NST * STG
    float* hpS  = smem + NST * STG;              // 2 * 256 (per half)
    float* waS  = hpS + 2 * DA;                  // 256 (shared)
    float* scS  = waS + DA;                      // 2 * 256 (per half)
    float* esS  = scS + 2 * DA;                  // 2 * 64
    float* misc = esS + 2 * 64;                  // 2 * 8

    const int th = threadIdx.x;
    const int half = th >> 8;                    // which batch of the pair
    const int t = th & 255;
    const int wid = t >> 5, lane = t & 31, g = lane >> 2, tg = lane & 3;
    const int warp_m = wid >> 2, warp_n = wid & 3;    // per-half 2x4 warps: 64 rows x 256 cols
    const int b = blockIdx.x * 2 + half;

    const float* vb0 = visual + (size_t)(blockIdx.x * 2)     * NR * DV;
    const float* vb1 = visual + (size_t)(blockIdx.x * 2 + 1) * NR * DV;
    const float* vb  = half ? vb1 : vb0;
    const float4* vb4 = (const float4*)vb;

    float* hpH  = hpS + half * DA;
    float* scH  = scS + half * DA;
    float* esH  = esS + half * 64;
    float* miscH = misc + half * 8;

    hpH[t] = g_hproj[b * DA + t] + bv[t];
    if (half == 0) waS[t] = Wa[t];
    scH[t] = 0.0f;
    if (t == 0) { miscH[0] = -3.0e38f; miscH[1] = 0.0f; miscH[2] = 0.0f; }

    const uint32_t sS = smem_u32(stg);

    // prologue: chunks 0,1 into stages 0,1
    stage_chunk(0, 0, sS, vb0, vb1, th); cpa_commit();
    stage_chunk(1, 1, sS, vb0, vb1, th); cpa_commit();

    float acc[2][8][4];
#pragma unroll
    for (int mf = 0; mf < 2; mf++)
#pragma unroll
        for (int nf = 0; nf < 8; nf++)
#pragma unroll
            for (int i = 0; i < 4; i++) acc[mf][nf][i] = 0.0f;

    float4 num = make_float4(0.f, 0.f, 0.f, 0.f);    // output dims 4t..4t+3 of batch b
    int buf = 0;

#pragma unroll 1
    for (int mc = 0; mc < 4; mc++) {
        // tail chunk rows 192..255: only 192..207 matter
        const int nmf = (mc == 3) ? ((warp_m == 0) ? 1 : 0) : 2;

        for (int kc = 0; kc < 32; kc++) {
            const int idx = mc * 32 + kc;
            if (idx == NCH - 1) cpa_wait<0>(); else cpa_wait<1>();   // chunk idx landed
            __syncthreads();                                          // single barrier per chunk
            if (idx + 2 < NCH) {
                int sbuf = (buf == 0) ? 2 : buf - 1;                  // == (idx+2)%3
                stage_chunk(idx + 2, sbuf, sS, vb0, vb1, th);
                cpa_commit();
            }

            const float*  A  = stg + buf * STG + half * A_STAGE + (warp_m * 32) * AP;
            const float4* Bf = (const float4*)(stg + buf * STG + 2 * A_STAGE)
                               + (warp_n * 4) * 32 + lane;
#pragma unroll
            for (int ks = 0; ks < 4; ks++) {
                const int kk = ks * 8;
                uint32_t a[2][4];
#pragma unroll
                for (int mf = 0; mf < 2; mf++) {
                    if (mf < nmf) {
                        const float* ar = A + (mf * 16 + g) * AP + kk + tg;
                        a[mf][0] = __float_as_uint(ar[0]);
                        a[mf][1] = __float_as_uint(ar[8 * AP]);
                        a[mf][2] = __float_as_uint(ar[4]);
                        a[mf][3] = __float_as_uint(ar[8 * AP + 4]);
                    }
                }
                const float4* Bk = Bf + (ks * 16) * 32;
#pragma unroll
                for (int m = 0; m < 4; m++) {
                    const float4 f = Bk[m * 32];
                    const uint32_t b00 = __float_as_uint(f.x), b01 = __float_as_uint(f.y);
                    const uint32_t b10 = __float_as_uint(f.z), b11 = __float_as_uint(f.w);
#pragma unroll
                    for (int mf = 0; mf < 2; mf++) {
                        if (mf < nmf) {
                            mma8(acc[mf][2 * m],     a[mf], b00, b01);
                            mma8(acc[mf][2 * m + 1], a[mf], b10, b11);
                        }
                    }
                }
            }
            buf = (buf == 2) ? 0 : buf + 1;
        }

        // ---- score epilogue (per half): relu(c+hp)*wa, reduce over 256 cols -> scH ----
        {
            float pA[2] = {0.0f, 0.0f}, pB[2] = {0.0f, 0.0f};
#pragma unroll
            for (int nf = 0; nf < 8; nf++) {
                const int col = warp_n * 64 + nf * 8 + 2 * tg;
                const float hp0 = hpH[col], hp1 = hpH[col + 1];
                const float wa0 = waS[col], wa1 = waS[col + 1];
#pragma unroll
                for (int mf = 0; mf < 2; mf++) {
                    if (mf < nmf) {
                        pA[mf] += fmaxf(acc[mf][nf][0] + hp0, 0.0f) * wa0
                                + fmaxf(acc[mf][nf][1] + hp1, 0.0f) * wa1;
                        pB[mf] += fmaxf(acc[mf][nf][2] + hp0, 0.0f) * wa0
                                + fmaxf(acc[mf][nf][3] + hp1, 0.0f) * wa1;
                        acc[mf][nf][0] = acc[mf][nf][1] = 0.0f;
                        acc[mf][nf][2] = acc[mf][nf][3] = 0.0f;
                    }
                }
            }
#pragma unroll
            for (int mf = 0; mf < 2; mf++) {
                if (mf < nmf) {
                    pA[mf] += __shfl_xor_sync(0xffffffffu, pA[mf], 1);
                    pA[mf] += __shfl_xor_sync(0xffffffffu, pA[mf], 2);
                    pB[mf] += __shfl_xor_sync(0xffffffffu, pB[mf], 1);
                    pB[mf] += __shfl_xor_sync(0xffffffffu, pB[mf], 2);
                    if (tg == 0) {
                        const int r0 = mc * MT + warp_m * 32 + mf * 16 + g;
                        atomicAdd(&scH[r0],     pA[mf]);
                        atomicAdd(&scH[r0 + 8], pB[mf]);
                    }
                }
            }
        }
        __syncthreads();       // scores of this chunk final (both halves)

        // ---- online softmax state update (warp 0 of each half) ----
        if (wid == 0) {
            const int r0 = mc * MT;
            float s0 = (r0 + lane      < NR) ? scH[r0 + lane]      : -3.0e38f;
            float s1 = (r0 + 32 + lane < NR) ? scH[r0 + 32 + lane] : -3.0e38f;
            float mx = fmaxf(s0, s1);
#pragma unroll
            for (int off = 16; off; off >>= 1)
                mx = fmaxf(mx, __shfl_xor_sync(0xffffffffu, mx, off));
            const float Mold = miscH[0];
            const float Mnew = fmaxf(Mold, mx);
            const float scl  = __expf(Mold - Mnew);   // first chunk: underflows to 0
            const float e0 = __expf(s0 - Mnew);
            const float e1 = __expf(s1 - Mnew);
            esH[lane]      = e0;
            esH[32 + lane] = e1;
            float se = e0 + e1;
#pragma unroll
            for (int off = 16; off; off >>= 1)
                se += __shfl_xor_sync(0xffffffffu, se, off);
            if (lane == 0) {
                miscH[1] = miscH[1] * scl + se;
                miscH[0] = Mnew;
                miscH[2] = scl;
            }
        }
        __syncthreads();

        // ---- numerator accumulation from L2-hot rows of this chunk (per half) ----
        {
            const float scl = miscH[2];
            const int nrr = (mc < 3) ? MT : (NR - 3 * MT);   // 64 or 4
            float4 s = make_float4(0.f, 0.f, 0.f, 0.f);
            for (int rr = 0; rr < nrr; rr++) {
                const float e = esH[rr];
                const float4 x = vb4[(size_t)(mc * MT + rr) * (DV / 4) + t];
                s.x = fmaf(e, x.x, s.x);
                s.y = fmaf(e, x.y, s.y);
                s.z = fmaf(e, x.z, s.z);
                s.w = fmaf(e, x.w, s.w);
            }
            num.x = fmaf(num.x, scl, s.x);
            num.y = fmaf(num.y, scl, s.y);
            num.z = fmaf(num.z, scl, s.z);
            num.w = fmaf(num.w, scl, s.w);
        }
        __syncthreads();       // esH/miscH stable before next chunk's epilogue
    }

    // ---- final: out = num / den ----
    const float inv = 1.0f / miscH[1];
    num.x *= inv; num.y *= inv; num.z *= inv; num.w *= inv;
    ((float4*)out)[(size_t)b * (DV / 4) + t] = num;
}

extern "C" void kernel_launch(void* const* d_in, const int* in_sizes, int n_in,
                              void* d_out, int out_size) {
    const float* visual = (const float*)d_in[0];
    const float* hidden = (const float*)d_in[1];
    const float* Wv     = (const float*)d_in[2];
    const float* bv     = (const float*)d_in[3];
    const float* Wh     = (const float*)d_in[4];
    const float* bh     = (const float*)d_in[5];
    const float* Wa     = (const float*)d_in[6];
    // d_in[7] = ba: additive constant over regions -> softmax-invariant, intentionally unused
    float* out = (float*)d_out;
    (void)in_sizes; (void)n_in; (void)out_size;

    cudaFuncSetAttribute(fused_kernel, cudaFuncAttributeMaxDynamicSharedMemorySize, SMEM_BYTES);

    setup_kernel<<<1536, DA>>>(Wv, hidden, Wh, bh);
    fused_kernel<<<NB / 2, TPB, SMEM_BYTES>>>(visual, bv, Wa, out);
}

// round 10
// speedup vs baseline: 1.4848x; 1.4848x over previous
#include <cuda_runtime.h>
#include <cuda_fp16.h>
#include <cstdint>

#define NB 512
#define NR 196
#define DV 1024
#define DH 512
#define DA 256
#define KC 32
#define TPB 256
#define AP 36                   // A smem pitch (fp32 floats)
#define MT 64                   // M tile rows per chunk
#define A_STAGE (MT * AP)       // 2304 floats
#define B_STAGE 4096            // u32 count of kc-slice of fp16 frag-major B (16KB)
#define STG (A_STAGE + B_STAGE) // 6400 floats per stage (25.6KB)
#define NST 3
#define NCH 128                 // 4 M-chunks x 32 K-chunks
#define SMEM_FLOATS (NST * STG + DA + DA + DA + 64 + 8)
#define SMEM_BYTES (SMEM_FLOATS * 4)

__device__ uint32_t g_Wvh[DV * DA / 2];   // fp16 Wv, B-fragment-major [kc][ks2][wn][nf][lane][b0,b1]
__device__ float g_hproj[NB * DA];

// ---------------- helpers ----------------
static __device__ __forceinline__ uint32_t smem_u32(const void* p) {
    uint32_t a;
    asm("{ .reg .u64 t; cvta.to.shared.u64 t, %1; cvt.u32.u64 %0, t; }" : "=r"(a) : "l"(p));
    return a;
}
static __device__ __forceinline__ void cpa16(uint32_t dst, const void* src) {
    asm volatile("cp.async.cg.shared.global [%0], [%1], 16;" :: "r"(dst), "l"(src));
}
static __device__ __forceinline__ void cpa_commit() {
    asm volatile("cp.async.commit_group;" ::: "memory");
}
template <int N> static __device__ __forceinline__ void cpa_wait() {
    asm volatile("cp.async.wait_group %0;" :: "n"(N) : "memory");
}
static __device__ __forceinline__ void sts_zero16(uint32_t dst) {
    asm volatile("st.shared.v4.b32 [%0], {%1,%1,%1,%1};" :: "r"(dst), "r"(0) : "memory");
}
static __device__ __forceinline__ uint32_t pack_h2(float lo, float hi) {
    __half2 h = __floats2half2_rn(lo, hi);
    return *(uint32_t*)&h;
}
static __device__ __forceinline__ void mma16(float* c, const uint32_t* a, uint32_t b0, uint32_t b1) {
    asm volatile(
        "mma.sync.aligned.m16n8k16.row.col.f32.f16.f16.f32 "
        "{%0,%1,%2,%3}, {%4,%5,%6,%7}, {%8,%9}, {%0,%1,%2,%3};"
        : "+f"(c[0]), "+f"(c[1]), "+f"(c[2]), "+f"(c[3])
        : "r"(a[0]), "r"(a[1]), "r"(a[2]), "r"(a[3]), "r"(b0), "r"(b1));
}

// ---------------- setup: Wv->fp16 frag-major (blocks 0..511) + hproj (512..1023) ----------------
// u32 entry r = kc*4096 + ks2*2048 + wn*512 + nf*64 + lane*2 + breg
// col = wn*64+nf*8+(lane>>2);  k0 = kc*32+ks2*16+2*(lane&3)+breg*8;  val = (h(Wv[k0][col]), h(Wv[k0+1][col]))
__global__ __launch_bounds__(DA) void setup_kernel(
    const float* __restrict__ Wv,
    const float* __restrict__ hidden, const float* __restrict__ Wh,
    const float* __restrict__ bh)
{
    if (blockIdx.x < 512) {
        const int r = blockIdx.x * DA + threadIdx.x;
        const int breg = r & 1;
        const int lane = (r >> 1) & 31;
        const int nf   = (r >> 6) & 7;
        const int wn   = (r >> 9) & 3;
        const int ks2  = (r >> 11) & 1;      // FIXED: bit 11 (was bit 12)
        const int kc   = r >> 12;            // FIXED: bits 12+ (was 13+)
        const int col = wn * 64 + nf * 8 + (lane >> 2);
        const int k0  = kc * 32 + ks2 * 16 + 2 * (lane & 3) + breg * 8;
        g_Wvh[r] = pack_h2(Wv[k0 * DA + col], Wv[(k0 + 1) * DA + col]);
    } else {
        const int b = blockIdx.x - 512, a = threadIdx.x;
        const float* h = hidden + b * DH;
        const float* w = Wh + a;
        float acc = bh[a];
#pragma unroll 8
        for (int k = 0; k < DH; k++) acc = fmaf(h[k], w[k * DA], acc);
        g_hproj[b * DA + a] = acc;
    }
}

// ---------------- staging: A fp32 (2 cpa16/thr) + B fp16 slice (4 cpa16/thr) ----------------
static __device__ __forceinline__ void stage_chunk(int idx, int sbuf, uint32_t sS,
                                                   const float* __restrict__ vb, int t) {
    const int mc = idx >> 5, kc = idx & 31;
    const int k0 = kc * KC;
    const uint32_t base = sS + (uint32_t)sbuf * (STG * 4);
#pragma unroll
    for (int i = 0; i < 2; i++) {                 // A: 64 rows x 8 segs of 16B
        int s = t + i * TPB;
        int row = s >> 3, seg = s & 7;
        int gr = mc * MT + row;
        uint32_t dst = base + row * (AP * 4) + seg * 16;
        if (gr < NR) cpa16(dst, vb + (size_t)gr * DV + k0 + seg * 4);
        else         sts_zero16(dst);
    }
    const uint32_t* bsrc = g_Wvh + (size_t)kc * B_STAGE;   // 16KB slice
    const uint32_t bB = base + (uint32_t)(A_STAGE * 4);
#pragma unroll
    for (int i = 0; i < 4; i++) {
        int s = t + i * TPB;
        cpa16(bB + s * 16, bsrc + s * 4);
    }
}

// ---------------- fused: 1 CTA/batch, 2 CTAs/SM, 3-stage 1-sync, fp16 MMA, online softmax ----------------
__global__ __launch_bounds__(TPB, 2) void fused_kernel(
    const float* __restrict__ visual,
    const float* __restrict__ bv,
    const float* __restrict__ Wa,
    float* __restrict__ out)
{
    extern __shared__ float smem[];
    float* stg  = smem;                          // NST * STG
    float* hpS  = smem + NST * STG;
    float* waS  = hpS + DA;
    float* scS  = waS + DA;
    float* esS  = scS + DA;                      // 64 exp weights of current chunk
    float* misc = esS + 64;                      // [0]=max,[1]=den,[2]=scale

    const int b = blockIdx.x, t = threadIdx.x;
    const int wid = t >> 5, lane = t & 31, g = lane >> 2, tg = lane & 3;
    const int warp_m = wid >> 2, warp_n = wid & 3;    // 2x4 warps: 64 rows x 256 cols
    const float* vb = visual + (size_t)b * NR * DV;
    const float4* vb4 = (const float4*)vb;

    hpS[t] = g_hproj[b * DA + t] + bv[t];
    waS[t] = Wa[t];
    scS[t] = 0.0f;
    if (t == 0) { misc[0] = -3.0e38f; misc[1] = 0.0f; misc[2] = 0.0f; }

    const uint32_t sS = smem_u32(stg);

    stage_chunk(0, 0, sS, vb, t); cpa_commit();
    stage_chunk(1, 1, sS, vb, t); cpa_commit();

    float acc[2][8][4];
#pragma unroll
    for (int mf = 0; mf < 2; mf++)
#pragma unroll
        for (int nf = 0; nf < 8; nf++)
#pragma unroll
            for (int i = 0; i < 4; i++) acc[mf][nf][i] = 0.0f;

    float4 num = make_float4(0.f, 0.f, 0.f, 0.f);
    int buf = 0;

#pragma unroll 1
    for (int mc = 0; mc < 4; mc++) {
        const int nmf = (mc == 3) ? ((warp_m == 0) ? 1 : 0) : 2;

        for (int kc = 0; kc < 32; kc++) {
            const int idx = mc * 32 + kc;
            if (idx == NCH - 1) cpa_wait<0>(); else cpa_wait<1>();   // chunk idx landed
            __syncthreads();                                          // single barrier per chunk
            if (idx + 2 < NCH) {
                int sbuf = (buf == 0) ? 2 : buf - 1;                  // == (idx+2)%3
                stage_chunk(idx + 2, sbuf, sS, vb, t);
                cpa_commit();
            }

            if (nmf > 0) {
                const float* A = stg + buf * STG + (warp_m * 32) * AP;
                const uint2* Bw = (const uint2*)(stg + buf * STG + A_STAGE)
                                  + (warp_n * 8) * 32 + lane;         // [wn][nf][lane]
#pragma unroll
                for (int ks2 = 0; ks2 < 2; ks2++) {
                    const int kk = ks2 * 16 + 2 * tg;
                    uint32_t a[2][4];
#pragma unroll
                    for (int mf = 0; mf < 2; mf++) {
                        if (mf < nmf) {
                            const float* ar = A + (mf * 16 + g) * AP + kk;
                            const float2 f0 = *(const float2*)(ar);
                            const float2 f1 = *(const float2*)(ar + 8 * AP);
                            const float2 f2 = *(const float2*)(ar + 8);
                            const float2 f3 = *(const float2*)(ar + 8 * AP + 8);
                            a[mf][0] = pack_h2(f0.x, f0.y);
                            a[mf][1] = pack_h2(f1.x, f1.y);
                            a[mf][2] = pack_h2(f2.x, f2.y);
                            a[mf][3] = pack_h2(f3.x, f3.y);
                        }
                    }
                    const uint2* Bk = Bw + ks2 * 1024;    // ks2 stride = 4*8*32 uint2
#pragma unroll
                    for (int nf = 0; nf < 8; nf++) {
                        const uint2 bb = Bk[nf * 32];
#pragma unroll
                        for (int mf = 0; mf < 2; mf++)
                            if (mf < nmf) mma16(acc[mf][nf], a[mf], bb.x, bb.y);
                    }
                }
            }
            buf = (buf == 2) ? 0 : buf + 1;
        }

        // ---- score epilogue: relu(c+hp)*wa, reduce over 256 cols -> scS ----
        {
            float pA[2] = {0.0f, 0.0f}, pB[2] = {0.0f, 0.0f};
#pragma unroll
            for (int nf = 0; nf < 8; nf++) {
                const int col = warp_n * 64 + nf * 8 + 2 * tg;
                const float hp0 = hpS[col], hp1 = hpS[col + 1];
                const float wa0 = waS[col], wa1 = waS[col + 1];
#pragma unroll
                for (int mf = 0; mf < 2; mf++) {
                    if (mf < nmf) {
                        pA[mf] += fmaxf(acc[mf][nf][0] + hp0, 0.0f) * wa0
                                + fmaxf(acc[mf][nf][1] + hp1, 0.0f) * wa1;
                        pB[mf] += fmaxf(acc[mf][nf][2] + hp0, 0.0f) * wa0
                                + fmaxf(acc[mf][nf][3] + hp1, 0.0f) * wa1;
                        acc[mf][nf][0] = acc[mf][nf][1] = 0.0f;
                        acc[mf][nf][2] = acc[mf][nf][3] = 0.0f;
                    }
                }
            }
#pragma unroll
            for (int mf = 0; mf < 2; mf++) {
                if (mf < nmf) {
                    pA[mf] += __shfl_xor_sync(0xffffffffu, pA[mf], 1);
                    pA[mf] += __shfl_xor_sync(0xffffffffu, pA[mf], 2);
                    pB[mf] += __shfl_xor_sync(0xffffffffu, pB[mf], 1);
                    pB[mf] += __shfl_xor_sync(0xffffffffu, pB[mf], 2);
                    if (tg == 0) {
                        const int r0 = mc * MT + warp_m * 32 + mf * 16 + g;
                        atomicAdd(&scS[r0],     pA[mf]);
                        atomicAdd(&scS[r0 + 8], pB[mf]);
                    }
                }
            }
        }
        __syncthreads();

        // ---- online softmax state update (warp 0) ----
        if (wid == 0) {
            const int r0 = mc * MT;
            float s0 = (r0 + lane      < NR) ? scS[r0 + lane]      : -3.0e38f;
            float s1 = (r0 + 32 + lane < NR) ? scS[r0 + 32 + lane] : -3.0e38f;
            float mx = fmaxf(s0, s1);
#pragma unroll
            for (int off = 16; off; off >>= 1)
                mx = fmaxf(mx, __shfl_xor_sync(0xffffffffu, mx, off));
            const float Mold = misc[0];
            const float Mnew = fmaxf(Mold, mx);
            const float scl  = __expf(Mold - Mnew);
            const float e0 = __expf(s0 - Mnew);
            const float e1 = __expf(s1 - Mnew);
            esS[lane]      = e0;
            esS[32 + lane] = e1;
            float se = e0 + e1;
#pragma unroll
            for (int off = 16; off; off >>= 1)
                se += __shfl_xor_sync(0xffffffffu, se, off);
            if (lane == 0) {
                misc[1] = misc[1] * scl + se;
                misc[0] = Mnew;
                misc[2] = scl;
            }
        }
        __syncthreads();

        // ---- numerator accumulation from L2-hot rows of this chunk ----
        {
            const float scl = misc[2];
            const int nrr = (mc < 3) ? MT : (NR - 3 * MT);   // 64 or 4
            float4 s = make_float4(0.f, 0.f, 0.f, 0.f);
            for (int rr = 0; rr < nrr; rr++) {
                const float e = esS[rr];
                const float4 x = vb4[(size_t)(mc * MT + rr) * (DV / 4) + t];
                s.x = fmaf(e, x.x, s.x);
                s.y = fmaf(e, x.y, s.y);
                s.z = fmaf(e, x.z, s.z);
                s.w = fmaf(e, x.w, s.w);
            }
            num.x = fmaf(num.x, scl, s.x);
            num.y = fmaf(num.y, scl, s.y);
            num.z = fmaf(num.z, scl, s.z);
            num.w = fmaf(num.w, scl, s.w);
        }
        __syncthreads();
    }

    const float inv = 1.0f / misc[1];
    num.x *= inv; num.y *= inv; num.z *= inv; num.w *= inv;
    ((float4*)out)[(size_t)b * (DV / 4) + t] = num;
}

extern "C" void kernel_launch(void* const* d_in, const int* in_sizes, int n_in,
                              void* d_out, int out_size) {
    const float* visual = (const float*)d_in[0];
    const float* hidden = (const float*)d_in[1];
    const float* Wv     = (const float*)d_in[2];
    const float* bv     = (const float*)d_in[3];
    const float* Wh     = (const float*)d_in[4];
    const float* bh     = (const float*)d_in[5];
    const float* Wa     = (const float*)d_in[6];
    // d_in[7] = ba: additive constant over regions -> softmax-invariant, intentionally unused
    float* out = (float*)d_out;
    (void)in_sizes; (void)n_in; (void)out_size;

    cudaFuncSetAttribute(fused_kernel, cudaFuncAttributeMaxDynamicSharedMemorySize, SMEM_BYTES);

    setup_kernel<<<1024, DA>>>(Wv, hidden, Wh, bh);
    fused_kernel<<<NB, TPB, SMEM_BYTES>>>(visual, bv, Wa, out);
}

// round 11
// speedup vs baseline: 1.5373x; 1.0353x over previous
#include <cuda_runtime.h>
#include <cuda_fp16.h>
#include <cstdint>

#define NB 512
#define NR 196
#define DV 1024
#define DH 512
#define DA 256
#define KC 64                   // K elements per chunk (doubled)
#define TPB 256
#define AP 68                   // A smem pitch (fp32 floats), == 4 mod 32 like proven AP=36
#define MT 64                   // M tile rows per chunk
#define A_STAGE (MT * AP)       // 4352 floats
#define B_STAGE 8192            // u32 count: 32KB = two contiguous 16KB kc-slices of fp16 B
#define STG (A_STAGE + B_STAGE) // 12544 floats per stage (50.2KB)
#define NCH 64                  // 4 M-chunks x 16 K-chunks
#define SMEM_FLOATS (2 * STG + DA + DA + DA + 64 + 8)
#define SMEM_BYTES (SMEM_FLOATS * 4)

__device__ uint32_t g_Wvh[DV * DA / 2];   // fp16 Wv, B-fragment-major [kc32][ks2][wn][nf][lane][b0,b1]
__device__ float g_hproj[NB * DA];

// ---------------- helpers ----------------
static __device__ __forceinline__ uint32_t smem_u32(const void* p) {
    uint32_t a;
    asm("{ .reg .u64 t; cvta.to.shared.u64 t, %1; cvt.u32.u64 %0, t; }" : "=r"(a) : "l"(p));
    return a;
}
static __device__ __forceinline__ void cpa16(uint32_t dst, const void* src) {
    asm volatile("cp.async.cg.shared.global [%0], [%1], 16;" :: "r"(dst), "l"(src));
}
static __device__ __forceinline__ void cpa_commit() {
    asm volatile("cp.async.commit_group;" ::: "memory");
}
template <int N> static __device__ __forceinline__ void cpa_wait() {
    asm volatile("cp.async.wait_group %0;" :: "n"(N) : "memory");
}
static __device__ __forceinline__ void sts_zero16(uint32_t dst) {
    asm volatile("st.shared.v4.b32 [%0], {%1,%1,%1,%1};" :: "r"(dst), "r"(0) : "memory");
}
static __device__ __forceinline__ uint32_t pack_h2(float lo, float hi) {
    __half2 h = __floats2half2_rn(lo, hi);
    return *(uint32_t*)&h;
}
static __device__ __forceinline__ void mma16(float* c, const uint32_t* a, uint32_t b0, uint32_t b1) {
    asm volatile(
        "mma.sync.aligned.m16n8k16.row.col.f32.f16.f16.f32 "
        "{%0,%1,%2,%3}, {%4,%5,%6,%7}, {%8,%9}, {%0,%1,%2,%3};"
        : "+f"(c[0]), "+f"(c[1]), "+f"(c[2]), "+f"(c[3])
        : "r"(a[0]), "r"(a[1]), "r"(a[2]), "r"(a[3]), "r"(b0), "r"(b1));
}

// ---------------- setup: Wv->fp16 frag-major (blocks 0..511) + hproj (512..1023) ----------------
// u32 entry r = kc32*4096 + ks2*2048 + wn*512 + nf*64 + lane*2 + breg
__global__ __launch_bounds__(DA) void setup_kernel(
    const float* __restrict__ Wv,
    const float* __restrict__ hidden, const float* __restrict__ Wh,
    const float* __restrict__ bh)
{
    if (blockIdx.x < 512) {
        const int r = blockIdx.x * DA + threadIdx.x;
        const int breg = r & 1;
        const int lane = (r >> 1) & 31;
        const int nf   = (r >> 6) & 7;
        const int wn   = (r >> 9) & 3;
        const int ks2  = (r >> 11) & 1;
        const int kc   = r >> 12;
        const int col = wn * 64 + nf * 8 + (lane >> 2);
        const int k0  = kc * 32 + ks2 * 16 + 2 * (lane & 3) + breg * 8;
        g_Wvh[r] = pack_h2(Wv[k0 * DA + col], Wv[(k0 + 1) * DA + col]);
    } else {
        const int b = blockIdx.x - 512, a = threadIdx.x;
        const float* h = hidden + b * DH;
        const float* w = Wh + a;
        float acc = bh[a];
#pragma unroll 8
        for (int k = 0; k < DH; k++) acc = fmaf(h[k], w[k * DA], acc);
        g_hproj[b * DA + a] = acc;
    }
}

// ---------------- staging: A fp32 (4 cpa16/thr) + B fp16 double-slice (8 cpa16/thr) ----------------
static __device__ __forceinline__ void stage_chunk(int idx, uint32_t sS,
                                                   const float* __restrict__ vb, int t) {
    const int mc = idx >> 4, kc = idx & 15, buf = idx & 1;
    const int k0 = kc * KC;
    const uint32_t base = sS + (uint32_t)buf * (STG * 4);
#pragma unroll
    for (int i = 0; i < 4; i++) {                 // A: 64 rows x 16 segs of 16B
        int s = t + i * TPB;
        int row = s >> 4, seg = s & 15;
        int gr = mc * MT + row;
        uint32_t dst = base + row * (AP * 4) + seg * 16;
        if (gr < NR) cpa16(dst, vb + (size_t)gr * DV + k0 + seg * 4);
        else         sts_zero16(dst);
    }
    const uint32_t* bsrc = g_Wvh + (size_t)(2 * kc) * 4096;   // two contiguous 16KB slices
    const uint32_t bB = base + (uint32_t)(A_STAGE * 4);
#pragma unroll
    for (int i = 0; i < 8; i++) {
        int s = t + i * TPB;
        cpa16(bB + s * 16, bsrc + s * 4);
    }
}

// ---------------- fused: 1 CTA/batch, 2 CTAs/SM, 2-stage, KC=64, fp16 MMA, online softmax ----------------
__global__ __launch_bounds__(TPB, 2) void fused_kernel(
    const float* __restrict__ visual,
    const float* __restrict__ bv,
    const float* __restrict__ Wa,
    float* __restrict__ out)
{
    extern __shared__ float smem[];
    float* stg  = smem;                          // 2 * STG
    float* hpS  = smem + 2 * STG;
    float* waS  = hpS + DA;
    float* scS  = waS + DA;
    float* esS  = scS + DA;                      // 64 exp weights of current chunk
    float* misc = esS + 64;                      // [0]=max,[1]=den,[2]=scale

    const int b = blockIdx.x, t = threadIdx.x;
    const int wid = t >> 5, lane = t & 31, g = lane >> 2, tg = lane & 3;
    const int warp_m = wid >> 2, warp_n = wid & 3;    // 2x4 warps: 64 rows x 256 cols
    const float* vb = visual + (size_t)b * NR * DV;
    const float4* vb4 = (const float4*)vb;

    hpS[t] = g_hproj[b * DA + t] + bv[t];
    waS[t] = Wa[t];
    scS[t] = 0.0f;
    if (t == 0) { misc[0] = -3.0e38f; misc[1] = 0.0f; misc[2] = 0.0f; }

    const uint32_t sS = smem_u32(stg);

    stage_chunk(0, sS, vb, t);
    cpa_commit();

    float acc[2][8][4];
#pragma unroll
    for (int mf = 0; mf < 2; mf++)
#pragma unroll
        for (int nf = 0; nf < 8; nf++)
#pragma unroll
            for (int i = 0; i < 4; i++) acc[mf][nf][i] = 0.0f;

    float4 num = make_float4(0.f, 0.f, 0.f, 0.f);

#pragma unroll 1
    for (int mc = 0; mc < 4; mc++) {
        const int nmf = (mc == 3) ? ((warp_m == 0) ? 1 : 0) : 2;

        for (int kc = 0; kc < 16; kc++) {
            const int idx = mc * 16 + kc;
            if (idx) __syncthreads();                  // WAR: restage target buffer drained
            if (idx + 1 < NCH) {
                stage_chunk(idx + 1, sS, vb, t);
                cpa_commit();
                cpa_wait<1>();                         // chunk idx landed (this thread)
            } else {
                cpa_wait<0>();
            }
            __syncthreads();                           // all threads' data landed

            if (nmf > 0) {
                const int buf = idx & 1;
                const float* A = stg + buf * STG + (warp_m * 32) * AP;
                const uint2* Bw = (const uint2*)(stg + buf * STG + A_STAGE)
                                  + (warp_n * 8) * 32 + lane;     // [wn][nf][lane]
#pragma unroll
                for (int ks2 = 0; ks2 < 4; ks2++) {
                    const int kk = ks2 * 16 + 2 * tg;
                    uint32_t a[2][4];
#pragma unroll
                    for (int mf = 0; mf < 2; mf++) {
                        if (mf < nmf) {
                            const float* ar = A + (mf * 16 + g) * AP + kk;
                            const float2 f0 = *(const float2*)(ar);
                            const float2 f1 = *(const float2*)(ar + 8 * AP);
                            const float2 f2 = *(const float2*)(ar + 8);
                            const float2 f3 = *(const float2*)(ar + 8 * AP + 8);
                            a[mf][0] = pack_h2(f0.x, f0.y);
                            a[mf][1] = pack_h2(f1.x, f1.y);
                            a[mf][2] = pack_h2(f2.x, f2.y);
                            a[mf][3] = pack_h2(f3.x, f3.y);
                        }
                    }
                    const uint2* Bk = Bw + ks2 * 1024;    // ks2 stride = one 16KB slice half
#pragma unroll
                    for (int nf = 0; nf < 8; nf++) {
                        const uint2 bb = Bk[nf * 32];
#pragma unroll
                        for (int mf = 0; mf < 2; mf++)
                            if (mf < nmf) mma16(acc[mf][nf], a[mf], bb.x, bb.y);
                    }
                }
            }
        }

        // ---- score epilogue: relu(c+hp)*wa, reduce over 256 cols -> scS ----
        {
            float pA[2] = {0.0f, 0.0f}, pB[2] = {0.0f, 0.0f};
#pragma unroll
            for (int nf = 0; nf < 8; nf++) {
                const int col = warp_n * 64 + nf * 8 + 2 * tg;
                const float hp0 = hpS[col], hp1 = hpS[col + 1];
                const float wa0 = waS[col], wa1 = waS[col + 1];
#pragma unroll
                for (int mf = 0; mf < 2; mf++) {
                    if (mf < nmf) {
                        pA[mf] += fmaxf(acc[mf][nf][0] + hp0, 0.0f) * wa0
                                + fmaxf(acc[mf][nf][1] + hp1, 0.0f) * wa1;
                        pB[mf] += fmaxf(acc[mf][nf][2] + hp0, 0.0f) * wa0
                                + fmaxf(acc[mf][nf][3] + hp1, 0.0f) * wa1;
                        acc[mf][nf][0] = acc[mf][nf][1] = 0.0f;
                        acc[mf][nf][2] = acc[mf][nf][3] = 0.0f;
                    }
                }
            }
#pragma unroll
            for (int mf = 0; mf < 2; mf++) {
                if (mf < nmf) {
                    pA[mf] += __shfl_xor_sync(0xffffffffu, pA[mf], 1);
                    pA[mf] += __shfl_xor_sync(0xffffffffu, pA[mf], 2);
                    pB[mf] += __shfl_xor_sync(0xffffffffu, pB[mf], 1);
                    pB[mf] += __shfl_xor_sync(0xffffffffu, pB[mf], 2);
                    if (tg == 0) {
                        const int r0 = mc * MT + warp_m * 32 + mf * 16 + g;
                        atomicAdd(&scS[r0],     pA[mf]);
                        atomicAdd(&scS[r0 + 8], pB[mf]);
                    }
                }
            }
        }
        __syncthreads();

        // ---- online softmax state update (warp 0) ----
        if (wid == 0) {
            const int r0 = mc * MT;
            float s0 = (r0 + lane      < NR) ? scS[r0 + lane]      : -3.0e38f;
            float s1 = (r0 + 32 + lane < NR) ? scS[r0 + 32 + lane] : -3.0e38f;
            float mx = fmaxf(s0, s1);
#pragma unroll
            for (int off = 16; off; off >>= 1)
                mx = fmaxf(mx, __shfl_xor_sync(0xffffffffu, mx, off));
            const float Mold = misc[0];
            const float Mnew = fmaxf(Mold, mx);
            const float scl  = __expf(Mold - Mnew);
            const float e0 = __expf(s0 - Mnew);
            const float e1 = __expf(s1 - Mnew);
            esS[lane]      = e0;
            esS[32 + lane] = e1;
            float se = e0 + e1;
#pragma unroll
            for (int off = 16; off; off >>= 1)
                se += __shfl_xor_sync(0xffffffffu, se, off);
            if (lane == 0) {
                misc[1] = misc[1] * scl + se;
                misc[0] = Mnew;
                misc[2] = scl;
            }
        }
        __syncthreads();

        // ---- numerator accumulation from L2-hot rows of this chunk ----
        {
            const float scl = misc[2];
            const int nrr = (mc < 3) ? MT : (NR - 3 * MT);   // 64 or 4
            float4 s = make_float4(0.f, 0.f, 0.f, 0.f);
            for (int rr = 0; rr < nrr; rr++) {
                const float e = esS[rr];
                const float4 x = vb4[(size_t)(mc * MT + rr) * (DV / 4) + t];
                s.x = fmaf(e, x.x, s.x);
                s.y = fmaf(e, x.y, s.y);
                s.z = fmaf(e, x.z, s.z);
                s.w = fmaf(e, x.w, s.w);
            }
            num.x = fmaf(num.x, scl, s.x);
            num.y = fmaf(num.y, scl, s.y);
            num.z = fmaf(num.z, scl, s.z);
            num.w = fmaf(num.w, scl, s.w);
        }
        __syncthreads();
    }

    const float inv = 1.0f / misc[1];
    num.x *= inv; num.y *= inv; num.z *= inv; num.w *= inv;
    ((float4*)out)[(size_t)b * (DV / 4) + t] = num;
}

extern "C" void kernel_launch(void* const* d_in, const int* in_sizes, int n_in,
                              void* d_out, int out_size) {
    const float* visual = (const float*)d_in[0];
    const float* hidden = (const float*)d_in[1];
    const float* Wv     = (const float*)d_in[2];
    const float* bv     = (const float*)d_in[3];
    const float* Wh     = (const float*)d_in[4];
    const float* bh     = (const float*)d_in[5];
    const float* Wa     = (const float*)d_in[6];
    // d_in[7] = ba: additive constant over regions -> softmax-invariant, intentionally unused
    float* out = (float*)d_out;
    (void)in_sizes; (void)n_in; (void)out_size;

    cudaFuncSetAttribute(fused_kernel, cudaFuncAttributeMaxDynamicSharedMemorySize, SMEM_BYTES);

    setup_kernel<<<1024, DA>>>(Wv, hidden, Wh, bh);
    fused_kernel<<<NB, TPB, SMEM_BYTES>>>(visual, bv, Wa, out);
}